// round 3
// baseline (speedup 1.0000x reference)
#include <cuda_runtime.h>
#include <cstdint>

#define NPTS 16384
#define CPB  64     // cols (gt points) per block, fixed per block
#define RPT  64     // rows (pred points) per tile
#define NSPLIT 2    // row-range splits (for occupancy)

__device__ float4 g_x[NPTS];      // pred points, w = |p|^2
__device__ float4 g_y[NPTS];      // gt points,   w = |p|^2
__device__ float  g_rowmin[NPTS]; // min_j d2 for each pred point
__device__ float  g_colmin[NPTS]; // min_i d2 for each gt point

#define F_INF __int_as_float(0x7f800000)

__device__ __forceinline__ void atomicMinF(float* addr, float val) {
    // sign-aware float atomic-min (valid with +INF init)
    if (val >= 0.0f) atomicMin((int*)addr, __float_as_int(val));
    else             atomicMax((unsigned int*)addr, __float_as_uint(val));
}

__global__ void chamfer_prep(const float* __restrict__ pred,
                             const float* __restrict__ gt) {
    int i = blockIdx.x * blockDim.x + threadIdx.x;
    if (i >= NPTS) return;
    float a = __ldg(&pred[i * 3 + 0]);
    float b = __ldg(&pred[i * 3 + 1]);
    float c = __ldg(&pred[i * 3 + 2]);
    g_x[i] = make_float4(a, b, c, fmaf(a, a, fmaf(b, b, c * c)));
    g_rowmin[i] = F_INF;
    float d = __ldg(&gt[i * 3 + 0]);
    float e = __ldg(&gt[i * 3 + 1]);
    float f = __ldg(&gt[i * 3 + 2]);
    g_y[i] = make_float4(d, e, f, fmaf(d, d, fmaf(e, e, f * f)));
    g_colmin[i] = F_INF;
}

// Block: 256 threads as 16(tx) x 16(ty). Thread owns 4 fixed cols (tx*4..+3)
// and, per row tile, 4 rows (ty*4..+3). Col-mins accumulate in registers
// across the entire row loop; row-mins are reduced per tile via shared mem
// and pushed with one atomic per row per (block,tile).
__global__ __launch_bounds__(256, 4) void chamfer_main() {
    __shared__ float4 xs[RPT];
    __shared__ float  red[64][17];   // padded to dodge bank conflicts

    const int tid = threadIdx.x;
    const int tx  = tid & 15;
    const int ty  = tid >> 4;
    const int colbase = blockIdx.x * CPB;

    // Fixed per-thread gt points (4 cols)
    float4 yv[4];
#pragma unroll
    for (int j = 0; j < 4; ++j) yv[j] = g_y[colbase + tx * 4 + j];

    float cmin[4] = {F_INF, F_INF, F_INF, F_INF};

    const int tiles_per_split = NPTS / RPT / NSPLIT;   // 128
    const int t0 = blockIdx.y * tiles_per_split;

    for (int t = 0; t < tiles_per_split; ++t) {
        const int rowbase = (t0 + t) * RPT;

        if (tid < RPT) xs[tid] = g_x[rowbase + tid];
        __syncthreads();                       // xs ready

        float rmin[4] = {F_INF, F_INF, F_INF, F_INF};
#pragma unroll
        for (int i = 0; i < 4; ++i) {
            float4 xr = xs[ty * 4 + i];        // LDS broadcast across tx
#pragma unroll
            for (int j = 0; j < 4; ++j) {
                float dot = fmaf(xr.z, yv[j].z, fmaf(xr.y, yv[j].y, xr.x * yv[j].x));
                rmin[i] = fminf(rmin[i], fmaf(dot, -2.0f, yv[j].w)); // d2 - x2
                cmin[j] = fminf(cmin[j], fmaf(dot, -2.0f, xr.w));    // d2 - y2
            }
        }

        // reduce rmin across the 16 tx lanes
#pragma unroll
        for (int i = 0; i < 4; ++i) red[ty * 4 + i][tx] = rmin[i];
        __syncthreads();                       // red ready
        if (tid < RPT) {
            float m = red[tid][0];
#pragma unroll
            for (int k = 1; k < 16; ++k) m = fminf(m, red[tid][k]);
            atomicMinF(&g_rowmin[rowbase + tid], m + xs[tid].w); // add back x2
        }
        __syncthreads();                       // red/xs reads done before reuse
    }

    // reduce cmin across the 16 ty lanes
#pragma unroll
    for (int j = 0; j < 4; ++j) red[tx * 4 + j][ty] = cmin[j];
    __syncthreads();
    if (tid < CPB) {
        float m = red[tid][0];
#pragma unroll
        for (int k = 1; k < 16; ++k) m = fminf(m, red[tid][k]);
        atomicMinF(&g_colmin[colbase + tid], m + g_y[colbase + tid].w); // add y2
    }
}

__global__ void chamfer_finalize(float* __restrict__ out) {
    __shared__ float warpsum[8];
    float s = 0.0f;
    for (int i = threadIdx.x; i < NPTS; i += 256) {
        s += sqrtf(fmaxf(g_rowmin[i], 0.0f));
        s += sqrtf(fmaxf(g_colmin[i], 0.0f));
    }
#pragma unroll
    for (int off = 16; off > 0; off >>= 1)
        s += __shfl_xor_sync(0xffffffffu, s, off);
    if ((threadIdx.x & 31) == 0) warpsum[threadIdx.x >> 5] = s;
    __syncthreads();
    if (threadIdx.x == 0) {
        float tot = 0.0f;
#pragma unroll
        for (int w = 0; w < 8; ++w) tot += warpsum[w];
        out[0] = tot * (1.0f / (float)NPTS);
    }
}

extern "C" void kernel_launch(void* const* d_in, const int* in_sizes, int n_in,
                              void* d_out, int out_size) {
    const float* pred = (const float*)d_in[0];
    const float* gt   = (const float*)d_in[1];
    float* out = (float*)d_out;

    chamfer_prep<<<(NPTS + 255) / 256, 256>>>(pred, gt);
    dim3 grid(NPTS / CPB, NSPLIT);   // (256, 2)
    chamfer_main<<<grid, 256>>>();
    chamfer_finalize<<<1, 256>>>(out);
}

// round 4
// speedup vs baseline: 1.0117x; 1.0117x over previous
#include <cuda_runtime.h>
#include <cstdint>

#define NPTS   16384
#define CPB    64                           // cols (gt points) per strip
#define RPT    128                          // rows (pred points) per tile
#define NCHUNK 16                           // row chunks (for fine-grained items)
#define CHUNK_ROWS (NPTS / NCHUNK)          // 1024
#define TILES_PER_CHUNK (CHUNK_ROWS / RPT)  // 8
#define NSTRIP (NPTS / CPB)                 // 256
#define NITEMS (NSTRIP * NCHUNK)            // 4096
#define GRID_MAIN 592                       // 148 SM x 4; extras exit on empty queue

__device__ float4 g_x[NPTS];      // pred, w = |p|^2
__device__ float4 g_y[NPTS];      // gt,   w = |p|^2
__device__ float  g_rowmin[NPTS];
__device__ float  g_colmin[NPTS];
__device__ unsigned int g_item;

#define F_INF __int_as_float(0x7f800000)

static __device__ __forceinline__ void atomicMinF(float* a, float v) {
    // sign-aware float atomic-min (valid with +INF init, mixed signs OK)
    if (v >= 0.0f) atomicMin((int*)a, __float_as_int(v));
    else           atomicMax((unsigned int*)a, __float_as_uint(v));
}

// ---- packed f32x2 helpers (Blackwell FFMA2; ptxas never auto-fuses) ----
static __device__ __forceinline__ unsigned long long pk2(float lo, float hi) {
    unsigned long long r;
    asm("mov.b64 %0, {%1, %2};" : "=l"(r) : "f"(lo), "f"(hi));
    return r;
}
static __device__ __forceinline__ void upk2(float& lo, float& hi, unsigned long long v) {
    asm("mov.b64 {%0, %1}, %2;" : "=f"(lo), "=f"(hi) : "l"(v));
}
static __device__ __forceinline__ unsigned long long f2fma(unsigned long long a,
                                                           unsigned long long b,
                                                           unsigned long long c) {
    unsigned long long d;
    asm("fma.rn.f32x2 %0, %1, %2, %3;" : "=l"(d) : "l"(a), "l"(b), "l"(c));
    return d;
}
static __device__ __forceinline__ unsigned long long f2mul(unsigned long long a,
                                                           unsigned long long b) {
    unsigned long long d;
    asm("mul.rn.f32x2 %0, %1, %2;" : "=l"(d) : "l"(a), "l"(b));
    return d;
}

__global__ void chamfer_prep(const float* __restrict__ pred,
                             const float* __restrict__ gt) {
    int i = blockIdx.x * blockDim.x + threadIdx.x;
    if (i == 0) g_item = 0u;
    if (i >= NPTS) return;
    float a = __ldg(&pred[i * 3 + 0]);
    float b = __ldg(&pred[i * 3 + 1]);
    float c = __ldg(&pred[i * 3 + 2]);
    g_x[i] = make_float4(a, b, c, fmaf(a, a, fmaf(b, b, c * c)));
    g_rowmin[i] = F_INF;
    float d = __ldg(&gt[i * 3 + 0]);
    float e = __ldg(&gt[i * 3 + 1]);
    float f = __ldg(&gt[i * 3 + 2]);
    g_y[i] = make_float4(d, e, f, fmaf(d, d, fmaf(e, e, f * f)));
    g_colmin[i] = F_INF;
}

// 256 threads = 16(tx) x 16(ty). Thread owns 4 fixed cols (tx*4..+3) whose
// broadcast packs are hoisted per item; per tile it owns 8 rows (ty*8..+7)
// processed as 4 packed row-pairs. Each pair of distances costs 5 FFMA2 (fma
// pipe) + 4 FMNMX (alu pipe). Col-mins live in registers across the whole
// item; row-mins are reduced via smem + one atomic per (row, item-tile).
// Work items pulled from a global counter to defeat wave quantization.
__global__ __launch_bounds__(256) void chamfer_main() {
    __shared__ float4 xs[RPT];
    __shared__ float  red[RPT][17];   // padded: stride 17 is bank-conflict-free
    __shared__ unsigned int s_item;

    const int tid = threadIdx.x;
    const int tx  = tid & 15;
    const int ty  = tid >> 4;
    const unsigned long long m2 = pk2(-2.0f, -2.0f);

    for (;;) {
        if (tid == 0) s_item = atomicAdd(&g_item, 1u);
        __syncthreads();
        const unsigned int item = s_item;
        if (item >= NITEMS) break;          // uniform: all threads see same item

        const int strip   = item & (NSTRIP - 1);
        const int chunk   = item >> 8;      // item / NSTRIP
        const int colbase = strip * CPB;

        // broadcast packs of this thread's 4 gt points (fixed for the item)
        unsigned long long bx[4], by[4], bz[4], bw[4];
#pragma unroll
        for (int j = 0; j < 4; ++j) {
            float4 y = g_y[colbase + tx * 4 + j];
            bx[j] = pk2(y.x, y.x); by[j] = pk2(y.y, y.y);
            bz[j] = pk2(y.z, y.z); bw[j] = pk2(y.w, y.w);
        }
        float cmin[4] = {F_INF, F_INF, F_INF, F_INF};

        for (int t = 0; t < TILES_PER_CHUNK; ++t) {
            const int rowbase = chunk * CHUNK_ROWS + t * RPT;
            if (tid < RPT) xs[tid] = g_x[rowbase + tid];
            __syncthreads();                // xs ready (also fences red reuse)

            float rm[8];
#pragma unroll
            for (int i = 0; i < 4; ++i) {
                float4 x0 = xs[ty * 8 + 2 * i];      // LDS broadcast over tx
                float4 x1 = xs[ty * 8 + 2 * i + 1];
                unsigned long long rx = pk2(x0.x, x1.x);
                unsigned long long ry = pk2(x0.y, x1.y);
                unsigned long long rz = pk2(x0.z, x1.z);
                unsigned long long rw = pk2(x0.w, x1.w);
                float rlo = F_INF, rhi = F_INF;
#pragma unroll
                for (int j = 0; j < 4; ++j) {
                    // packed over the 2 rows: dot, then (-2dot + y2), (-2dot + x2)
                    unsigned long long d2 = f2fma(rz, bz[j],
                                              f2fma(ry, by[j], f2mul(rx, bx[j])));
                    unsigned long long r2 = f2fma(d2, m2, bw[j]);
                    unsigned long long c2 = f2fma(d2, m2, rw);
                    float a, b, c, d;
                    upk2(a, b, r2); rlo = fminf(rlo, a); rhi = fminf(rhi, b);
                    upk2(c, d, c2); cmin[j] = fminf(cmin[j], fminf(c, d));
                }
                rm[2 * i]     = rlo + x0.w;   // add back x2
                rm[2 * i + 1] = rhi + x1.w;
            }

#pragma unroll
            for (int i = 0; i < 8; ++i) red[ty * 8 + i][tx] = rm[i];
            __syncthreads();                // red ready
            if (tid < RPT) {
                float m = red[tid][0];
#pragma unroll
                for (int k = 1; k < 16; ++k) m = fminf(m, red[tid][k]);
                atomicMinF(&g_rowmin[rowbase + tid], m);
            }
            __syncthreads();                // red reads done before reuse
        }

        // flush this item's col-mins (add back y2)
#pragma unroll
        for (int j = 0; j < 4; ++j) red[tx * 4 + j][ty] = cmin[j];
        __syncthreads();
        if (tid < CPB) {
            float m = red[tid][0];
#pragma unroll
            for (int k = 1; k < 16; ++k) m = fminf(m, red[tid][k]);
            atomicMinF(&g_colmin[colbase + tid], m + g_y[colbase + tid].w);
        }
        __syncthreads();                    // red/s_item safe for next item
    }
}

__global__ void chamfer_finalize(float* __restrict__ out) {
    __shared__ float warpsum[8];
    float s = 0.0f;
    for (int i = threadIdx.x; i < NPTS; i += 256) {
        s += sqrtf(fmaxf(g_rowmin[i], 0.0f));
        s += sqrtf(fmaxf(g_colmin[i], 0.0f));
    }
#pragma unroll
    for (int off = 16; off > 0; off >>= 1)
        s += __shfl_xor_sync(0xffffffffu, s, off);
    if ((threadIdx.x & 31) == 0) warpsum[threadIdx.x >> 5] = s;
    __syncthreads();
    if (threadIdx.x == 0) {
        float tot = 0.0f;
#pragma unroll
        for (int w = 0; w < 8; ++w) tot += warpsum[w];
        out[0] = tot * (1.0f / (float)NPTS);
    }
}

extern "C" void kernel_launch(void* const* d_in, const int* in_sizes, int n_in,
                              void* d_out, int out_size) {
    const float* pred = (const float*)d_in[0];
    const float* gt   = (const float*)d_in[1];
    float* out = (float*)d_out;

    chamfer_prep<<<(NPTS + 255) / 256, 256>>>(pred, gt);
    chamfer_main<<<GRID_MAIN, 256>>>();
    chamfer_finalize<<<1, 256>>>(out);
}